// round 16
// baseline (speedup 1.0000x reference)
#include <cuda_runtime.h>
#include <cuda_bf16.h>
#include <cstdint>

#define B_    128
#define T_    512
#define D_    256
#define H_    1024
#define G4_   4096
#define Z_    128
#define NBLK  128
#define NTHR  256        // 8 warps = 4 m-pairs x 2 k-halves

// dynamic smem map (bytes)
#define SM_B      1024                 // 80 ktiles * 2048 B (fragment-order) = 160 KB
#define SM_RED    164864               // k-split reduction scratch (16 KB)
#define SM_SIZE   181248

// ---------------- persistent device state ----------------
__device__ __align__(16) __nv_bfloat16 g_Ub[(size_t)NBLK * 81920];     // frag-order B
__device__ __align__(16) char g_xf[(size_t)T_ * 8 * 8 * 2048];         // x frags (64 MB)
__device__ __align__(16) char g_hf[2][32 * 8 * 2048];                  // h frags (512 KB x2)
__device__ float         g_h32[(size_t)B_ * H_];
__device__ unsigned int  g_bar;

// ---------------- helpers ----------------
__device__ __forceinline__ uint32_t smem_u32(const void* p) {
    uint32_t a;
    asm("{ .reg .u64 t; cvta.to.shared.u64 t, %1; cvt.u32.u64 %0, t; }" : "=r"(a) : "l"(p));
    return a;
}
__device__ __forceinline__ void cp_async16(uint32_t dst, const void* src) {
    asm volatile("cp.async.cg.shared.global [%0], [%1], 16;" :: "r"(dst), "l"(src) : "memory");
}
__device__ __forceinline__ void mma_bf16(float* d, const uint32_t* a, uint32_t b0, uint32_t b1) {
    asm volatile(
        "mma.sync.aligned.m16n8k16.row.col.f32.bf16.bf16.f32 "
        "{%0,%1,%2,%3}, {%4,%5,%6,%7}, {%8,%9}, {%0,%1,%2,%3};"
        : "+f"(d[0]), "+f"(d[1]), "+f"(d[2]), "+f"(d[3])
        : "r"(a[0]), "r"(a[1]), "r"(a[2]), "r"(a[3]), "r"(b0), "r"(b1));
}
__device__ __forceinline__ void st_cg_u32(void* p, uint32_t v) {
    asm volatile("st.global.cg.u32 [%0], %1;" :: "l"(p), "r"(v) : "memory");
}
__device__ __forceinline__ float sigmoid_f(float x) { return 1.0f / (1.0f + expf(-x)); }
__device__ __forceinline__ float softplus_f(float x) {
    return fmaxf(x, 0.0f) + log1pf(expf(-fabsf(x)));
}

// ---------------- prep kernels (unchanged layouts, validated R10/R15) ----------------
__global__ void reset_kernel() {
    int i = blockIdx.x * blockDim.x + threadIdx.x;
    if (i == 0) g_bar = 0u;
    uint4* p = (uint4*)&g_hf[0][0];
    for (int e = i; e < (int)(sizeof(g_hf[0]) / 16); e += gridDim.x * blockDim.x)
        p[e] = make_uint4(0, 0, 0, 0);
}

__global__ void xprep_kernel(const float* __restrict__ x) {
    size_t e = (size_t)blockIdx.x * blockDim.x + threadIdx.x;   // < B*T*D
    float v = x[e];
    __nv_bfloat16 hi = __float2bfloat16(v);
    __nv_bfloat16 lo = __float2bfloat16(v - __bfloat162float(hi));
    int b = (int)(e / ((size_t)T_ * D_));
    int r = (int)(e % ((size_t)T_ * D_));
    int t = r / D_, d = r % D_;
    int m = b >> 4, rl = b & 15;
    int c = d >> 5, kk = d & 31, sub = kk >> 4, k16 = kk & 15;
    int lane = (rl & 7) * 4 + ((k16 & 7) >> 1);
    int ee   = (rl >> 3) + 2 * (k16 >> 3);
    int i    = k16 & 1;
    size_t off = (((size_t)(t * 8 + c) * 8 + m) * 2048) + sub * 1024 + lane * 16 + ee * 4 + i * 2;
    *(__nv_bfloat16*)(g_xf + off)       = hi;   // hl=0
    *(__nv_bfloat16*)(g_xf + off + 512) = lo;   // hl=1
}

__global__ void uprep_kernel(const float* __restrict__ W, const float* __restrict__ U) {
    size_t id = (size_t)blockIdx.x * blockDim.x + threadIdx.x;   // < 128*40960
    int bid = (int)(id / 40960);
    int r   = (int)(id % 40960);
    int kt   = r >> 9;
    int r2   = r & 511;
    int half = r2 >> 8;
    int lane = (r2 >> 3) & 31;
    int e    = r2 & 7;
    int nip = e >> 2, rg = (e >> 1) & 1, i = e & 1;
    int k = kt * 16 + (lane & 3) * 2 + rg * 8 + i;
    int n = (half * 2 + nip) * 8 + (lane >> 2);
    int gcol = (n >> 3) * H_ + bid * 8 + (n & 7);
    float v = (k < 256) ? W[(size_t)k * G4_ + gcol]
                        : U[(size_t)(k - 256) * G4_ + gcol];
    __nv_bfloat16 hi = __float2bfloat16(v);
    __nv_bfloat16 lo = __float2bfloat16(v - __bfloat162float(hi));
    __nv_bfloat16* base = g_Ub + (size_t)bid * 81920 +
                          (size_t)((kt * 2 + half) * 2) * 256 + lane * 8 + e;
    base[0]   = hi;
    base[256] = lo;
}

// ---------------- A load (2 mtiles, 8 x LDG.128) and chunk compute ----------------
#define LOADA_X(S, P) do {                                 \
    sl[S][0] = __ldg((const uint4*)(P));                   \
    sl[S][1] = __ldg((const uint4*)((P) + 512));           \
    sl[S][2] = __ldg((const uint4*)((P) + 1024));          \
    sl[S][3] = __ldg((const uint4*)((P) + 1536));          \
    sl[S][4] = __ldg((const uint4*)((P) + 2048));          \
    sl[S][5] = __ldg((const uint4*)((P) + 2560));          \
    sl[S][6] = __ldg((const uint4*)((P) + 3072));          \
    sl[S][7] = __ldg((const uint4*)((P) + 3584));          \
} while (0)
#define LOADA_H(S, P) do {                                 \
    sl[S][0] = __ldcg((const uint4*)(P));                  \
    sl[S][1] = __ldcg((const uint4*)((P) + 512));          \
    sl[S][2] = __ldcg((const uint4*)((P) + 1024));         \
    sl[S][3] = __ldcg((const uint4*)((P) + 1536));         \
    sl[S][4] = __ldcg((const uint4*)((P) + 2048));         \
    sl[S][5] = __ldcg((const uint4*)((P) + 2560));         \
    sl[S][6] = __ldcg((const uint4*)((P) + 3072));         \
    sl[S][7] = __ldcg((const uint4*)((P) + 3584));         \
} while (0)
#define CHUNK(S, C) do {                                                      \
    const char* _bb0 = bB + (C) * 4096;                                       \
    _Pragma("unroll")                                                         \
    for (int sub = 0; sub < 2; sub++) {                                       \
        const char* bb = _bb0 + sub * 2048;                                   \
        uint4 h0 = *(const uint4*)(bb);                                       \
        uint4 l0 = *(const uint4*)(bb + 512);                                 \
        uint4 h1 = *(const uint4*)(bb + 1024);                                \
        uint4 l1 = *(const uint4*)(bb + 1536);                                \
        uint32_t bh[4][2] = {{h0.x,h0.y},{h0.z,h0.w},{h1.x,h1.y},{h1.z,h1.w}};\
        uint32_t bl[4][2] = {{l0.x,l0.y},{l0.z,l0.w},{l1.x,l1.y},{l1.z,l1.w}};\
        _Pragma("unroll")                                                     \
        for (int mt = 0; mt < 2; mt++) {                                      \
            const uint32_t* ah = (const uint32_t*)&sl[S][mt * 4 + sub * 2];   \
            const uint32_t* al = (const uint32_t*)&sl[S][mt * 4 + sub * 2 + 1];\
            _Pragma("unroll")                                                 \
            for (int nt = 0; nt < 4; nt++) {                                  \
                mma_bf16(acc[mt][nt], ah, bh[nt][0], bh[nt][1]);              \
                mma_bf16(acc[mt][nt], al, bh[nt][0], bh[nt][1]);              \
                mma_bf16(acc[mt][nt], ah, bl[nt][0], bl[nt][1]);              \
            }                                                                 \
        }                                                                     \
    }                                                                         \
} while (0)

// ---------------- main persistent kernel ----------------
__global__ void __launch_bounds__(NTHR, 1)
lstm_kernel(const float* __restrict__ bias)
{
    extern __shared__ char smem[];
    const uint32_t sb = smem_u32(smem);
    const int tid  = threadIdx.x;
    const int w    = tid >> 5;
    const int lane = tid & 31;
    const int mp   = w & 3;            // m-pair: rows [32mp, 32mp+32)
    const int kh   = w >> 2;           // k-half
    const int bid  = blockIdx.x;
    const int j0   = bid * 8;

    // Load resident fragment-order B (160 KB) once.
    {
        const char* src = (const char*)(g_Ub + (size_t)bid * 81920);
        for (int i = tid; i < 10240; i += NTHR)
            cp_async16(sb + SM_B + i * 16, src + (size_t)i * 16);
        asm volatile("cp.async.commit_group;\n\tcp.async.wait_group 0;" ::: "memory");
    }
    __syncthreads();

    // hoisted pointers (mtile0 base; mtile1 = +2048)
    const char* pxA  = g_xf    + (size_t)(2 * mp) * 2048 + lane * 16;
    const char* phA0 = g_hf[0] + (size_t)(2 * mp) * 2048 + lane * 16;
    const char* phA1 = g_hf[1] + (size_t)(2 * mp) * 2048 + lane * 16;
    const char* bB   = smem + SM_B + lane * 16;

    float bR[4][2];
#pragma unroll
    for (int g = 0; g < 4; g++)
#pragma unroll
        for (int p = 0; p < 2; p++)
            bR[g][p] = bias[g * H_ + j0 + (lane & 3) * 2 + p];

    float creg[8];
#pragma unroll
    for (int i = 0; i < 8; i++) creg[i] = 0.f;

    uint4 sl[2][8];
    // prologue: list idx 0,1 of t=0 (x chunks kh*4, kh*4+1)
    LOADA_X(0, pxA + (size_t)(kh * 4 + 0) * 16384);
    LOADA_X(1, pxA + (size_t)(kh * 4 + 1) * 16384);

    for (int t = 0; t < T_; t++) {
        const char* ph = (t & 1) ? phA1 : phA0;
        const size_t xbase = (size_t)t * 131072;

        float acc[2][4][4];
#pragma unroll
        for (int mt = 0; mt < 2; mt++)
#pragma unroll
            for (int nt = 0; nt < 4; nt++)
#pragma unroll
                for (int i = 0; i < 4; i++) acc[mt][nt][i] = 0.f;

#pragma unroll 2
        for (int i = 0; i < 20; i++) {
            if (i == 2 && t) {   // before first h-load issue (end of i==2)
                const unsigned target = (unsigned)t * (unsigned)NBLK;
                while (*(volatile unsigned*)&g_bar < target) { __nanosleep(32); }
                __threadfence();
            }
            const int c = (i < 4) ? (kh * 4 + i) : ((i - 4) * 2 + kh + 8);
            CHUNK(i & 1, c);
            const int j = i + 2;
            if (j < 4) {
                LOADA_X(i & 1, pxA + xbase + (size_t)(kh * 4 + j) * 16384);
            } else if (j < 20) {
                LOADA_H(i & 1, ph + (size_t)((j - 4) * 2 + kh) * 16384);
            } else if (t + 1 < T_) {
                LOADA_X(i & 1, pxA + xbase + 131072 + (size_t)(kh * 4 + j - 20) * 16384);
            }
        }

        // ---- k-half reduction through smem scratch ----
        if (kh == 1) {
#pragma unroll
            for (int mt = 0; mt < 2; mt++)
#pragma unroll
                for (int nt = 0; nt < 4; nt++)
                    *(float4*)(smem + SM_RED + mp * 4096 + (mt * 4 + nt) * 512 +
                               lane * 16) = *(const float4*)acc[mt][nt];
        }
        __syncthreads();

        // ---- epilogue (kh==0): reduce, bias, cell update, write h frags ----
        if (kh == 0) {
#pragma unroll
            for (int mt = 0; mt < 2; mt++)
#pragma unroll
                for (int nt = 0; nt < 4; nt++) {
                    float4 o = *(const float4*)(smem + SM_RED + mp * 4096 +
                                                (mt * 4 + nt) * 512 + lane * 16);
                    acc[mt][nt][0] += o.x; acc[mt][nt][1] += o.y;
                    acc[mt][nt][2] += o.z; acc[mt][nt][3] += o.w;
                }
            char* hfB = g_hf[(t + 1) & 1] + ((size_t)(bid >> 2) * 8) * 2048 +
                        ((bid >> 1) & 1) * 1024 + lane * 16 + (bid & 1) * 8;
#pragma unroll
            for (int mt = 0; mt < 2; mt++) {
                char* wh = hfB + (size_t)(2 * mp + mt) * 2048;
#pragma unroll
                for (int rs = 0; rs < 2; rs++) {
                    const int row = 32 * mp + 16 * mt + (lane >> 2) + rs * 8;
                    __nv_bfloat16 hhi[2], hlo[2];
#pragma unroll
                    for (int p = 0; p < 2; p++) {
                        const int ai = rs * 2 + p;
                        float gi = acc[mt][0][ai] + bR[0][p];
                        float gf = acc[mt][1][ai] + bR[1][p];
                        float gg = acc[mt][2][ai] + bR[2][p];
                        float go = acc[mt][3][ai] + bR[3][p];
                        float iv = sigmoid_f(gi), fv = sigmoid_f(gf), ov = sigmoid_f(go);
                        float gv = softplus_f(gg);
                        const int ci = mt * 4 + rs * 2 + p;
                        float cn = fv * creg[ci] + iv * gv;
                        creg[ci] = cn;
                        float hn = ov * softplus_f(cn);
                        hhi[p] = __float2bfloat16(hn);
                        hlo[p] = __float2bfloat16(hn - __bfloat162float(hhi[p]));
                        if (t == T_ - 1)
                            g_h32[(size_t)row * H_ + j0 + (lane & 3) * 2 + p] = hn;
                    }
                    uint32_t phi = (uint32_t)__bfloat16_as_ushort(hhi[0]) |
                                   ((uint32_t)__bfloat16_as_ushort(hhi[1]) << 16);
                    uint32_t plo = (uint32_t)__bfloat16_as_ushort(hlo[0]) |
                                   ((uint32_t)__bfloat16_as_ushort(hlo[1]) << 16);
                    st_cg_u32(wh + rs * 4,       phi);   // hl=0
                    st_cg_u32(wh + 512 + rs * 4, plo);   // hl=1
                }
            }
        }

        // ---- release h writes; wait happens next step at i==2 ----
        __syncthreads();
        if (tid == 0) {
            __threadfence();
            atomicAdd(&g_bar, 1u);
        }
    }
}

// ---------------- final projections (fp32) ----------------
__global__ void __launch_bounds__(Z_)
proj_kernel(const float* __restrict__ Wm, const float* __restrict__ bm,
            const float* __restrict__ Wv, const float* __restrict__ bv,
            const float* __restrict__ eps, float* __restrict__ out)
{
    __shared__ float hs[H_];
    const int b = blockIdx.x;
    const int z = threadIdx.x;
    const float* hrow = g_h32 + (size_t)b * H_;
    for (int k = z; k < H_; k += Z_) hs[k] = hrow[k];
    __syncthreads();

    float am = bm[z];
    float av = bv[z];
#pragma unroll 4
    for (int k = 0; k < H_; k++) {
        float hk = hs[k];
        am += hk * Wm[(size_t)k * Z_ + z];
        av += hk * Wv[(size_t)k * Z_ + z];
    }
    float zz = am + eps[(size_t)b * Z_ + z] * expf(0.5f * av);
    out[(size_t)b * Z_ + z]                 = am;
    out[(size_t)(B_ * Z_) + b * Z_ + z]     = av;
    out[(size_t)(2 * B_ * Z_) + b * Z_ + z] = zz;
}

// ---------------------------------------------------------------------------
extern "C" void kernel_launch(void* const* d_in, const int* in_sizes, int n_in,
                              void* d_out, int out_size)
{
    const float* x   = (const float*)d_in[0];
    const float* W   = (const float*)d_in[1];
    const float* U   = (const float*)d_in[2];
    const float* b   = (const float*)d_in[3];
    const float* Wm  = (const float*)d_in[4];
    const float* bm  = (const float*)d_in[5];
    const float* Wv  = (const float*)d_in[6];
    const float* bv  = (const float*)d_in[7];
    const float* eps = (const float*)d_in[8];
    float* out = (float*)d_out;

    cudaFuncSetAttribute(lstm_kernel, cudaFuncAttributeMaxDynamicSharedMemorySize, SM_SIZE);

    reset_kernel<<<256, 256>>>();
    xprep_kernel<<<(B_ * T_ * D_) / 256, 256>>>(x);
    uprep_kernel<<<(NBLK * 40960) / 256, 256>>>(W, U);
    lstm_kernel<<<NBLK, NTHR, SM_SIZE>>>(b);
    proj_kernel<<<B_, Z_>>>(Wm, bm, Wv, bv, eps, out);
}

// round 17
// speedup vs baseline: 1.0293x; 1.0293x over previous
#include <cuda_runtime.h>
#include <cuda_bf16.h>
#include <cstdint>

#define B_    128
#define T_    512
#define D_    256
#define H_    1024
#define G4_   4096
#define Z_    128
#define NBLK  128
#define NTHR  256        // 8 warps; warp w owns rows [16w,16w+16)

// dynamic smem map (bytes): B only
#define SM_B      1024                 // 80 ktiles * 2048 B (fragment-order) = 160 KB
#define SM_SIZE   165888

// ---------------- persistent device state ----------------
// A fragment-order blocks: [chunk][mtile(8)] x 2048 B, inner (sub2,hl2,lane32,e4 words)
__device__ __align__(16) __nv_bfloat16 g_Ub[(size_t)NBLK * 81920];     // frag-order B
__device__ __align__(16) char g_xf[(size_t)T_ * 8 * 8 * 2048];         // x frags (64 MB)
__device__ __align__(16) char g_hf[2][32 * 8 * 2048];                  // h frags (512 KB x2)
__device__ float         g_h32[(size_t)B_ * H_];
__device__ unsigned int  g_bar;

// ---------------- helpers ----------------
__device__ __forceinline__ uint32_t smem_u32(const void* p) {
    uint32_t a;
    asm("{ .reg .u64 t; cvta.to.shared.u64 t, %1; cvt.u32.u64 %0, t; }" : "=r"(a) : "l"(p));
    return a;
}
__device__ __forceinline__ void cp_async16(uint32_t dst, const void* src) {
    asm volatile("cp.async.cg.shared.global [%0], [%1], 16;" :: "r"(dst), "l"(src) : "memory");
}
__device__ __forceinline__ void mma_bf16(float* d, const uint32_t* a, uint32_t b0, uint32_t b1) {
    asm volatile(
        "mma.sync.aligned.m16n8k16.row.col.f32.bf16.bf16.f32 "
        "{%0,%1,%2,%3}, {%4,%5,%6,%7}, {%8,%9}, {%0,%1,%2,%3};"
        : "+f"(d[0]), "+f"(d[1]), "+f"(d[2]), "+f"(d[3])
        : "r"(a[0]), "r"(a[1]), "r"(a[2]), "r"(a[3]), "r"(b0), "r"(b1));
}
__device__ __forceinline__ void st_cg_u32(void* p, uint32_t v) {
    asm volatile("st.global.cg.u32 [%0], %1;" :: "l"(p), "r"(v) : "memory");
}
__device__ __forceinline__ float sigmoid_f(float x) { return 1.0f / (1.0f + expf(-x)); }
__device__ __forceinline__ float softplus_f(float x) {
    return fmaxf(x, 0.0f) + log1pf(expf(-fabsf(x)));
}

// ---------------- prep kernels (unchanged, validated R10/R15) ----------------
__global__ void reset_kernel() {
    int i = blockIdx.x * blockDim.x + threadIdx.x;
    if (i == 0) g_bar = 0u;
    uint4* p = (uint4*)&g_hf[0][0];
    for (int e = i; e < (int)(sizeof(g_hf[0]) / 16); e += gridDim.x * blockDim.x)
        p[e] = make_uint4(0, 0, 0, 0);
}

// x[B,T,D] fp32 -> g_xf fragment order
__global__ void xprep_kernel(const float* __restrict__ x) {
    size_t e = (size_t)blockIdx.x * blockDim.x + threadIdx.x;   // < B*T*D
    float v = x[e];
    __nv_bfloat16 hi = __float2bfloat16(v);
    __nv_bfloat16 lo = __float2bfloat16(v - __bfloat162float(hi));
    int b = (int)(e / ((size_t)T_ * D_));
    int r = (int)(e % ((size_t)T_ * D_));
    int t = r / D_, d = r % D_;
    int m = b >> 4, rl = b & 15;
    int c = d >> 5, kk = d & 31, sub = kk >> 4, k16 = kk & 15;
    int lane = (rl & 7) * 4 + ((k16 & 7) >> 1);
    int ee   = (rl >> 3) + 2 * (k16 >> 3);
    int i    = k16 & 1;
    size_t off = (((size_t)(t * 8 + c) * 8 + m) * 2048) + sub * 1024 + lane * 16 + ee * 4 + i * 2;
    *(__nv_bfloat16*)(g_xf + off)       = hi;   // hl=0
    *(__nv_bfloat16*)(g_xf + off + 512) = lo;   // hl=1
}

__global__ void uprep_kernel(const float* __restrict__ W, const float* __restrict__ U) {
    size_t id = (size_t)blockIdx.x * blockDim.x + threadIdx.x;   // < 128*40960
    int bid = (int)(id / 40960);
    int r   = (int)(id % 40960);
    int kt   = r >> 9;
    int r2   = r & 511;
    int half = r2 >> 8;
    int lane = (r2 >> 3) & 31;
    int e    = r2 & 7;
    int nip = e >> 2, rg = (e >> 1) & 1, i = e & 1;
    int k = kt * 16 + (lane & 3) * 2 + rg * 8 + i;
    int n = (half * 2 + nip) * 8 + (lane >> 2);
    int gcol = (n >> 3) * H_ + bid * 8 + (n & 7);
    float v = (k < 256) ? W[(size_t)k * G4_ + gcol]
                        : U[(size_t)(k - 256) * G4_ + gcol];
    __nv_bfloat16 hi = __float2bfloat16(v);
    __nv_bfloat16 lo = __float2bfloat16(v - __bfloat162float(hi));
    __nv_bfloat16* base = g_Ub + (size_t)bid * 81920 +
                          (size_t)((kt * 2 + half) * 2) * 256 + lane * 8 + e;
    base[0]   = hi;
    base[256] = lo;
}

// ---------------- chunk macros ----------------
#define LOADX(S, P) do {                                  \
    sl[S][0] = __ldg((const uint4*)(P));                  \
    sl[S][1] = __ldg((const uint4*)((P) + 512));          \
    sl[S][2] = __ldg((const uint4*)((P) + 1024));         \
    sl[S][3] = __ldg((const uint4*)((P) + 1536));         \
} while (0)
#define LOADH(S, P) do {                                  \
    sl[S][0] = __ldcg((const uint4*)(P));                 \
    sl[S][1] = __ldcg((const uint4*)((P) + 512));         \
    sl[S][2] = __ldcg((const uint4*)((P) + 1024));        \
    sl[S][3] = __ldcg((const uint4*)((P) + 1536));        \
} while (0)
#define CHUNK(S, BPTR, ACC) do {                                              \
    _Pragma("unroll")                                                         \
    for (int sub = 0; sub < 2; sub++) {                                       \
        const char* bb = (BPTR) + sub * 2048;                                 \
        uint4 h0 = *(const uint4*)(bb);                                       \
        uint4 l0 = *(const uint4*)(bb + 512);                                 \
        uint4 h1 = *(const uint4*)(bb + 1024);                                \
        uint4 l1 = *(const uint4*)(bb + 1536);                                \
        const uint32_t* ah = (const uint32_t*)&sl[S][sub * 2];                \
        const uint32_t* al = (const uint32_t*)&sl[S][sub * 2 + 1];            \
        uint32_t bh[4][2] = {{h0.x,h0.y},{h0.z,h0.w},{h1.x,h1.y},{h1.z,h1.w}};\
        uint32_t bl[4][2] = {{l0.x,l0.y},{l0.z,l0.w},{l1.x,l1.y},{l1.z,l1.w}};\
        _Pragma("unroll")                                                     \
        for (int nt = 0; nt < 4; nt++) {                                      \
            mma_bf16(ACC[nt], ah, bh[nt][0], bh[nt][1]);                      \
            mma_bf16(ACC[nt], al, bh[nt][0], bh[nt][1]);                      \
            mma_bf16(ACC[nt], ah, bl[nt][0], bl[nt][1]);                      \
        }                                                                     \
    }                                                                         \
} while (0)

// ---------------- main persistent kernel ----------------
__global__ void __launch_bounds__(NTHR, 1)
lstm_kernel(const float* __restrict__ bias)
{
    extern __shared__ char smem[];
    const uint32_t sb = smem_u32(smem);
    const int tid  = threadIdx.x;
    const int w    = tid >> 5;          // 0..7, owns rows [16w, 16w+16)
    const int lane = tid & 31;
    const int bid  = blockIdx.x;
    const int j0   = bid * 8;

    // Load resident fragment-order B (160 KB) once.
    {
        const char* src = (const char*)(g_Ub + (size_t)bid * 81920);
        for (int i = tid; i < 10240; i += NTHR)
            cp_async16(sb + SM_B + i * 16, src + (size_t)i * 16);
        asm volatile("cp.async.commit_group;\n\tcp.async.wait_group 0;" ::: "memory");
    }
    __syncthreads();

    // hoisted per-thread pointers
    const char* pxB  = g_xf    + w * 2048 + lane * 16;
    const char* phB0 = g_hf[0] + w * 2048 + lane * 16;
    const char* phB1 = g_hf[1] + w * 2048 + lane * 16;
    const char* bB   = smem + SM_B + lane * 16;

    float bR[4][2];
#pragma unroll
    for (int g = 0; g < 4; g++)
#pragma unroll
        for (int p = 0; p < 2; p++)
            bR[g][p] = bias[g * H_ + j0 + (lane & 3) * 2 + p];

    float creg[4];
#pragma unroll
    for (int i = 0; i < 4; i++) creg[i] = 0.f;

    uint4 sl[4][4];
    float acc[4][4], acc2[4][4];

    // prologue: x-chunks 0..3 of t=0, then phase A of t=0
#pragma unroll
    for (int s = 0; s < 4; s++) LOADX(s, pxB + s * 16384);
#pragma unroll
    for (int nt = 0; nt < 4; nt++)
#pragma unroll
        for (int i = 0; i < 4; i++) acc[nt][i] = 0.f;
    CHUNK(0, bB,         acc);  LOADX(0, pxB + 4 * 16384);
    CHUNK(1, bB + 4096,  acc);  LOADX(1, pxB + 5 * 16384);
    CHUNK(2, bB + 8192,  acc);  LOADX(2, pxB + 6 * 16384);
    CHUNK(3, bB + 12288, acc);  LOADX(3, pxB + 7 * 16384);

    for (int t = 0; t < T_; t++) {
        const char* ph  = (t & 1) ? phB1 : phB0;
        const char* pxn = pxB + (size_t)(t + 1) * 131072;

        // ---- barrier wait (covered by phase A'b chunks issued last iter) ----
        if (t) {
            const unsigned target = (unsigned)t * (unsigned)NBLK;
            while (*(volatile unsigned*)&g_bar < target) { __nanosleep(32); }
            __threadfence();
        }

        // ---- phase B: chunks 4..35; load h-chunks 0..31 ----
        {
            const char* bp = bB + 4 * 4096;
            const char* hp = ph;
#pragma unroll 1
            for (int gg = 0; gg < 8; gg++) {
                CHUNK(0, bp,         acc);  LOADH(0, hp);
                CHUNK(1, bp + 4096,  acc);  LOADH(1, hp + 16384);
                CHUNK(2, bp + 8192,  acc);  LOADH(2, hp + 32768);
                CHUNK(3, bp + 12288, acc);  LOADH(3, hp + 49152);
                bp += 16384; hp += 65536;
            }
            // ---- phase C: chunks 36..39; prefetch next step's x-chunks 0..3 ----
            const char* bp2 = bB + 36 * 4096;
            if (t + 1 < T_) {
                CHUNK(0, bp2,         acc);  LOADX(0, pxn);
                CHUNK(1, bp2 + 4096,  acc);  LOADX(1, pxn + 16384);
                CHUNK(2, bp2 + 8192,  acc);  LOADX(2, pxn + 32768);
                CHUNK(3, bp2 + 12288, acc);  LOADX(3, pxn + 49152);
            } else {
                CHUNK(0, bp2, acc); CHUNK(1, bp2 + 4096, acc);
                CHUNK(2, bp2 + 8192, acc); CHUNK(3, bp2 + 12288, acc);
            }
        }

        // ---- phase A'a (t+1): chunks 0..1 into acc2 — keeps tensor fed
        //      through the epilogue below ----
#pragma unroll
        for (int nt = 0; nt < 4; nt++)
#pragma unroll
            for (int i = 0; i < 4; i++) acc2[nt][i] = 0.f;
        if (t + 1 < T_) {
            CHUNK(0, bB,        acc2);  LOADX(0, pxn + 4 * 16384);
            CHUNK(1, bB + 4096, acc2);  LOADX(1, pxn + 5 * 16384);
        }

        // ---- epilogue: cell update; write h frags for consumers ----
        {
            // writer target: c=bid>>2, m=w, sub=(bid>>1)&1, lane'=lane, e=rs+2*(bid&1)
            char* wh = g_hf[(t + 1) & 1] +
                       ((size_t)(bid >> 2) * 8 + w) * 2048 +
                       ((bid >> 1) & 1) * 1024 + lane * 16 + (bid & 1) * 8;
#pragma unroll
            for (int rs = 0; rs < 2; rs++) {
                const int row = w * 16 + (lane >> 2) + rs * 8;
                __nv_bfloat16 hhi[2], hlo[2];
#pragma unroll
                for (int p = 0; p < 2; p++) {
                    const int ai = rs * 2 + p;
                    float gi = acc[0][ai] + bR[0][p];
                    float gf = acc[1][ai] + bR[1][p];
                    float gg = acc[2][ai] + bR[2][p];
                    float go = acc[3][ai] + bR[3][p];
                    float iv = sigmoid_f(gi), fv = sigmoid_f(gf), ov = sigmoid_f(go);
                    float gv = softplus_f(gg);
                    const int ci = rs * 2 + p;
                    float cn = fv * creg[ci] + iv * gv;
                    creg[ci] = cn;
                    float hn = ov * softplus_f(cn);
                    hhi[p] = __float2bfloat16(hn);
                    hlo[p] = __float2bfloat16(hn - __bfloat162float(hhi[p]));
                    if (t == T_ - 1)
                        g_h32[(size_t)row * H_ + j0 + (lane & 3) * 2 + p] = hn;
                }
                uint32_t phi = (uint32_t)__bfloat16_as_ushort(hhi[0]) |
                               ((uint32_t)__bfloat16_as_ushort(hhi[1]) << 16);
                uint32_t plo = (uint32_t)__bfloat16_as_ushort(hlo[0]) |
                               ((uint32_t)__bfloat16_as_ushort(hlo[1]) << 16);
                st_cg_u32(wh + rs * 4,       phi);   // hl=0
                st_cg_u32(wh + 512 + rs * 4, plo);   // hl=1
            }
        }

        // ---- release h writes ----
        __syncthreads();
        if (tid == 0) {
            __threadfence();
            atomicAdd(&g_bar, 1u);
        }

        // ---- phase A'b (t+1): chunks 2..3 into acc2 — covers barrier skew ----
        if (t + 1 < T_) {
            CHUNK(2, bB + 8192,  acc2);  LOADX(2, pxn + 6 * 16384);
            CHUNK(3, bB + 12288, acc2);  LOADX(3, pxn + 7 * 16384);
        }

        // hand over accumulators for next iteration
#pragma unroll
        for (int nt = 0; nt < 4; nt++)
#pragma unroll
            for (int i = 0; i < 4; i++) acc[nt][i] = acc2[nt][i];
    }
}

// ---------------- final projections (fp32) ----------------
__global__ void __launch_bounds__(Z_)
proj_kernel(const float* __restrict__ Wm, const float* __restrict__ bm,
            const float* __restrict__ Wv, const float* __restrict__ bv,
            const float* __restrict__ eps, float* __restrict__ out)
{
    __shared__ float hs[H_];
    const int b = blockIdx.x;
    const int z = threadIdx.x;
    const float* hrow = g_h32 + (size_t)b * H_;
    for (int k = z; k < H_; k += Z_) hs[k] = hrow[k];
    __syncthreads();

    float am = bm[z];
    float av = bv[z];
#pragma unroll 4
    for (int k = 0; k < H_; k++) {
        float hk = hs[k];
        am += hk * Wm[(size_t)k * Z_ + z];
        av += hk * Wv[(size_t)k * Z_ + z];
    }
    float zz = am + eps[(size_t)b * Z_ + z] * expf(0.5f * av);
    out[(size_t)b * Z_ + z]                 = am;
    out[(size_t)(B_ * Z_) + b * Z_ + z]     = av;
    out[(size_t)(2 * B_ * Z_) + b * Z_ + z] = zz;
}

// ---------------------------------------------------------------------------
extern "C" void kernel_launch(void* const* d_in, const int* in_sizes, int n_in,
                              void* d_out, int out_size)
{
    const float* x   = (const float*)d_in[0];
    const float* W   = (const float*)d_in[1];
    const float* U   = (const float*)d_in[2];
    const float* b   = (const float*)d_in[3];
    const float* Wm  = (const float*)d_in[4];
    const float* bm  = (const float*)d_in[5];
    const float* Wv  = (const float*)d_in[6];
    const float* bv  = (const float*)d_in[7];
    const float* eps = (const float*)d_in[8];
    float* out = (float*)d_out;

    cudaFuncSetAttribute(lstm_kernel, cudaFuncAttributeMaxDynamicSharedMemorySize, SM_SIZE);

    reset_kernel<<<256, 256>>>();
    xprep_kernel<<<(B_ * T_ * D_) / 256, 256>>>(x);
    uprep_kernel<<<(NBLK * 40960) / 256, 256>>>(W, U);
    lstm_kernel<<<NBLK, NTHR, SM_SIZE>>>(b);
    proj_kernel<<<B_, Z_>>>(Wm, bm, Wv, bv, eps, out);
}